// round 1
// baseline (speedup 1.0000x reference)
#include <cuda_runtime.h>
#include <cuda_bf16.h>

// SimilarityAttentionFusion: the distance bias (-|q-k| * 770000) makes every
// off-diagonal softmax weight exp(-770000+eps) == 0.0f exactly (fp32 underflow
// begins at exp(-87)). The attention matrix is exactly the identity, so
//   output[b,q,:] == global_embedding[b,q,:]   (bitwise, in fp32)
// The kernel is therefore a pure HBM-bound device copy of d_in[0].

__global__ void sim_attn_copy_kernel(const float4* __restrict__ src,
                                     float4* __restrict__ dst,
                                     long long n4) {
    long long i = (long long)blockIdx.x * blockDim.x + threadIdx.x;
    if (i < n4) {
        dst[i] = src[i];
    }
}

// Tail copy for any elements not divisible by 4 (not needed for this shape,
// 1024*77*768 is divisible by 4, but kept for safety at negligible cost).
__global__ void sim_attn_copy_tail(const float* __restrict__ src,
                                   float* __restrict__ dst,
                                   long long start, long long n) {
    long long i = start + (long long)blockIdx.x * blockDim.x + threadIdx.x;
    if (i < n) {
        dst[i] = src[i];
    }
}

extern "C" void kernel_launch(void* const* d_in, const int* in_sizes, int n_in,
                              void* d_out, int out_size) {
    const float* global_emb = (const float*)d_in[0];  // K = V tensor
    float* out = (float*)d_out;

    long long n  = (long long)out_size;       // 1024*77*768 = 60,555,264
    long long n4 = n / 4;                     // float4 count
    long long rem_start = n4 * 4;

    const int threads = 256;
    long long blocks4 = (n4 + threads - 1) / threads;
    sim_attn_copy_kernel<<<(unsigned)blocks4, threads>>>(
        (const float4*)global_emb, (float4*)out, n4);

    if (rem_start < n) {
        long long rem = n - rem_start;
        long long blocksr = (rem + threads - 1) / threads;
        sim_attn_copy_tail<<<(unsigned)blocksr, threads>>>(
            global_emb, out, rem_start, n);
    }
}

// round 4
// speedup vs baseline: 1.0129x; 1.0129x over previous
#include <cuda_runtime.h>
#include <cuda_bf16.h>

// SimilarityAttentionFusion: the distance bias (-|q-k| * 770000) makes every
// off-diagonal softmax weight exp(-770000+eps) == 0.0f exactly (fp32 underflow
// begins at exp(-87)). The attention matrix is exactly the identity, so
//   output[b,q,:] == global_embedding[b,q,:]   (bitwise, in fp32)
// The kernel is a pure HBM-bound device copy of d_in[0].
//
// R2: streaming cache hints (__ldcs/__stcs -> LDG.E.CS/STG.E.CS) to stop
// thrashing L2 with a zero-reuse 484MB stream, plus 4x grid-strided float4
// per thread (front-batched loads, MLP=4) and an exact-fit grid with no
// bounds predicate on the hot path.

static const int THREADS = 256;
static const int UNROLL  = 4;

// Hot path: n4 divisible by THREADS*UNROLL -> no bounds checks.
__global__ void sim_attn_copy4x(const float4* __restrict__ src,
                                float4* __restrict__ dst,
                                long long stride) {
    long long i = (long long)blockIdx.x * blockDim.x + threadIdx.x;
    // Front-batch 4 independent streaming loads (MLP=4), then 4 stores.
    float4 a = __ldcs(src + i);
    float4 b = __ldcs(src + i + stride);
    float4 c = __ldcs(src + i + 2 * stride);
    float4 d = __ldcs(src + i + 3 * stride);
    __stcs(dst + i, a);
    __stcs(dst + i + stride, b);
    __stcs(dst + i + 2 * stride, c);
    __stcs(dst + i + 3 * stride, d);
}

// Generic guarded fallback (not launched for this shape).
__global__ void sim_attn_copy_guarded(const float* __restrict__ src,
                                      float* __restrict__ dst,
                                      long long n) {
    long long i = (long long)blockIdx.x * blockDim.x + threadIdx.x;
    long long stride = (long long)gridDim.x * blockDim.x;
    for (; i < n; i += stride) {
        dst[i] = __ldcs(src + i);
    }
}

extern "C" void kernel_launch(void* const* d_in, const int* in_sizes, int n_in,
                              void* d_out, int out_size) {
    const float* global_emb = (const float*)d_in[0];  // K = V tensor
    float* out = (float*)d_out;

    long long n  = (long long)out_size;   // 1024*77*768 = 60,555,264
    long long n4 = n / 4;                 // 15,138,816 float4s

    const long long chunk = (long long)THREADS * UNROLL;
    if ((n % 4 == 0) && (n4 % chunk == 0)) {
        long long total_threads = n4 / UNROLL;          // 3,784,704
        long long blocks = total_threads / THREADS;     // 14,784 (exact)
        sim_attn_copy4x<<<(unsigned)blocks, THREADS>>>(
            (const float4*)global_emb, (float4*)out, total_threads);
    } else {
        long long blocks = (n + THREADS - 1) / THREADS;
        if (blocks > 59136) blocks = 59136;
        sim_attn_copy_guarded<<<(unsigned)blocks, THREADS>>>(
            global_emb, out, n);
    }
}